// round 1
// baseline (speedup 1.0000x reference)
#include <cuda_runtime.h>
#include <cstdint>

// Problem constants
#define NB    2
#define NS    2048
#define ND    2048
#define NH    16
#define NKVH  4
#define NDH   128
#define NREP  (NH / NKVH)      // 4
#define NROWS (NB * NS)        // 4096
#define NKVD  (NKVH * NDH)     // 512

// Scratch (static device globals: allocation-free)
__device__ float g_q[(size_t)NROWS * ND];    // 32 MB  (B,S,H,Dh)
__device__ float g_k[(size_t)NROWS * NKVD];  //  8 MB  (B,S,KVH,Dh)
__device__ float g_v[(size_t)NROWS * NKVD];  //  8 MB
__device__ float g_o[(size_t)NROWS * ND];    // 32 MB  attention out, (B,S,H*Dh)

// ---------------------------------------------------------------------------
// SGEMM: C[M,N] = A[M,K] @ W[N,K]^T   (both A and W are K-major row-major)
// Block tile 128x128, BK=16, 256 threads, 8x8 per-thread microtile.
// ---------------------------------------------------------------------------
__global__ __launch_bounds__(256, 2)
void sgemm_nt(const float* __restrict__ A, const float* __restrict__ W,
              float* __restrict__ C, int M, int N, int K)
{
    __shared__ float As[16][128];   // transposed: As[k][m]
    __shared__ float Bs[16][128];   // transposed: Bs[k][n]

    const int m0 = blockIdx.y * 128;
    const int n0 = blockIdx.x * 128;
    const int t  = threadIdx.x;
    const int tx = t & 15;
    const int ty = t >> 4;

    const int lrow = t >> 2;          // 0..63
    const int lcol = (t & 3) << 2;    // 0,4,8,12

    float acc[8][8];
#pragma unroll
    for (int i = 0; i < 8; ++i)
#pragma unroll
        for (int j = 0; j < 8; ++j) acc[i][j] = 0.0f;

    for (int k0 = 0; k0 < K; k0 += 16) {
#pragma unroll
        for (int half = 0; half < 2; ++half) {
            const int row = lrow + half * 64;
            float4 a = *(const float4*)(A + (size_t)(m0 + row) * K + k0 + lcol);
            As[lcol + 0][row] = a.x; As[lcol + 1][row] = a.y;
            As[lcol + 2][row] = a.z; As[lcol + 3][row] = a.w;
            float4 b = *(const float4*)(W + (size_t)(n0 + row) * K + k0 + lcol);
            Bs[lcol + 0][row] = b.x; Bs[lcol + 1][row] = b.y;
            Bs[lcol + 2][row] = b.z; Bs[lcol + 3][row] = b.w;
        }
        __syncthreads();

#pragma unroll
        for (int kk = 0; kk < 16; ++kk) {
            float af[8], bf[8];
            *(float4*)(af)     = *(const float4*)&As[kk][ty * 8];
            *(float4*)(af + 4) = *(const float4*)&As[kk][ty * 8 + 4];
            *(float4*)(bf)     = *(const float4*)&Bs[kk][tx * 8];
            *(float4*)(bf + 4) = *(const float4*)&Bs[kk][tx * 8 + 4];
#pragma unroll
            for (int i = 0; i < 8; ++i)
#pragma unroll
                for (int j = 0; j < 8; ++j)
                    acc[i][j] += af[i] * bf[j];
        }
        __syncthreads();
    }

#pragma unroll
    for (int i = 0; i < 8; ++i) {
        float4* cp = (float4*)(C + (size_t)(m0 + ty * 8 + i) * N + n0 + tx * 8);
        cp[0] = make_float4(acc[i][0], acc[i][1], acc[i][2], acc[i][3]);
        cp[1] = make_float4(acc[i][4], acc[i][5], acc[i][6], acc[i][7]);
    }
}

// ---------------------------------------------------------------------------
// RoPE over q (16 heads) and k (4 heads). Pair i uses elements 2i, 2i+1.
// ---------------------------------------------------------------------------
__global__ void rope_kernel(const float* __restrict__ fc, const float* __restrict__ fs)
{
    int idx = blockIdx.x * blockDim.x + threadIdx.x;
    const int QP = NROWS * NH * (NDH / 2);
    const int KPAIRS = NROWS * NKVH * (NDH / 2);

    float* base;
    int hcount;
    if (idx < QP) {
        base = g_q; hcount = NH;
    } else if (idx < QP + KPAIRS) {
        idx -= QP; base = g_k; hcount = NKVH;
    } else {
        return;
    }
    const int i  = idx & 63;      // pair index within head dim
    const int rh = idx >> 6;      // row*hcount + h
    const int row = rh / hcount;
    const int s = row & (NS - 1);

    const float c  = fc[s * 64 + i];
    const float sn = fs[s * 64 + i];
    float* p = base + (size_t)rh * NDH + 2 * i;
    const float xr = p[0], xi = p[1];
    p[0] = xr * c - xi * sn;
    p[1] = xr * sn + xi * c;
}

// ---------------------------------------------------------------------------
// Flash attention, fp32, causal, GQA (head h reads kv head h/NREP).
// Tile: 64 q-rows x 64 k-cols, Dh=128. 256 threads (16x16):
//   scores: thread owns 4x4 of the 64x64 tile (rows ty*4.., cols tx*4..)
//   output: thread owns 4 rows x 8 cols of the 64x128 O tile (cols tx*8..)
// K is stored TRANSPOSED in smem (pitch 68) -> conflict-light score loop.
// P tile aliases the Kt region (Kt dead after score phase).
// ---------------------------------------------------------------------------
#define KTP 68
#define ATTN_SMEM ((64 * 128 + 128 * KTP + 64 * 128) * 4)   // 100352 B

__global__ __launch_bounds__(256, 2)
void attn_kernel()
{
    extern __shared__ float sm[];
    float* Qs = sm;                      // [64][128]
    float* Kt = Qs + 64 * 128;           // [128][KTP]  (transposed K)
    float* Vs = Kt + 128 * KTP;          // [64][128]
    float* Ps = Kt;                      // alias: [64][64], valid after scores

    const int qb = blockIdx.x;           // q tile index, 0..31
    const int h  = blockIdx.y;
    const int b  = blockIdx.z;
    const int kvh = h / NREP;

    const int t  = threadIdx.x;
    const int tx = t & 15;
    const int ty = t >> 4;
    const int r0 = ty << 2;              // score/O row base
    const int c0 = tx << 2;              // score col base
    const int oc = tx << 3;              // O col base

    const float scale = 0.08838834764831845f;   // 1/sqrt(128)

    // Load Q tile (coalesced float4)
    for (int i = t; i < 64 * 32; i += 256) {
        const int r = i >> 5, d4 = (i & 31) << 2;
        *(float4*)&Qs[r * 128 + d4] =
            *(const float4*)&g_q[(size_t)(b * NS + qb * 64 + r) * ND + h * NDH + d4];
    }

    float m_i[4], l_i[4], acc[4][8];
#pragma unroll
    for (int i = 0; i < 4; ++i) {
        m_i[i] = -3.0e38f; l_i[i] = 0.0f;
#pragma unroll
        for (int c = 0; c < 8; ++c) acc[i][c] = 0.0f;
    }

    for (int jb = 0; jb <= qb; ++jb) {
        __syncthreads();   // prev iter done reading Ps/Vs before overwrite
        // Load K (transposed) and V tiles
        for (int i = t; i < 64 * 32; i += 256) {
            const int r = i >> 5, d4 = (i & 31) << 2;
            const size_t grow = (size_t)(b * NS + jb * 64 + r) * NKVD + kvh * NDH + d4;
            float4 k4 = *(const float4*)&g_k[grow];
            Kt[(d4 + 0) * KTP + r] = k4.x;
            Kt[(d4 + 1) * KTP + r] = k4.y;
            Kt[(d4 + 2) * KTP + r] = k4.z;
            Kt[(d4 + 3) * KTP + r] = k4.w;
            *(float4*)&Vs[r * 128 + d4] = *(const float4*)&g_v[grow];
        }
        __syncthreads();

        // Scores: S[r][c] = sum_d Q[r][d] * K[c][d]
        float s[4][4];
#pragma unroll
        for (int i = 0; i < 4; ++i)
#pragma unroll
            for (int j = 0; j < 4; ++j) s[i][j] = 0.0f;

        for (int d = 0; d < 128; d += 4) {
            float4 q0 = *(const float4*)&Qs[(r0 + 0) * 128 + d];
            float4 q1 = *(const float4*)&Qs[(r0 + 1) * 128 + d];
            float4 q2 = *(const float4*)&Qs[(r0 + 2) * 128 + d];
            float4 q3 = *(const float4*)&Qs[(r0 + 3) * 128 + d];
            float4 k0 = *(const float4*)&Kt[(d + 0) * KTP + c0];
            float4 k1 = *(const float4*)&Kt[(d + 1) * KTP + c0];
            float4 k2 = *(const float4*)&Kt[(d + 2) * KTP + c0];
            float4 k3 = *(const float4*)&Kt[(d + 3) * KTP + c0];
#define SCORE_ROW(i, q)                                                    \
            s[i][0] += q.x * k0.x + q.y * k1.x + q.z * k2.x + q.w * k3.x;  \
            s[i][1] += q.x * k0.y + q.y * k1.y + q.z * k2.y + q.w * k3.y;  \
            s[i][2] += q.x * k0.z + q.y * k1.z + q.z * k2.z + q.w * k3.z;  \
            s[i][3] += q.x * k0.w + q.y * k1.w + q.z * k2.w + q.w * k3.w;
            SCORE_ROW(0, q0)
            SCORE_ROW(1, q1)
            SCORE_ROW(2, q2)
            SCORE_ROW(3, q3)
#undef SCORE_ROW
        }

        __syncthreads();   // all threads done reading Kt -> Ps alias is safe

        const bool diag = (jb == qb);
#pragma unroll
        for (int i = 0; i < 4; ++i) {
#pragma unroll
            for (int j = 0; j < 4; ++j) {
                s[i][j] *= scale;
                if (diag && (c0 + j > r0 + i)) s[i][j] = -3.0e38f;
            }
            // row max across the 16 threads owning this row (lanes share ty)
            float mt = fmaxf(fmaxf(s[i][0], s[i][1]), fmaxf(s[i][2], s[i][3]));
#pragma unroll
            for (int o = 8; o >= 1; o >>= 1)
                mt = fmaxf(mt, __shfl_xor_sync(0xffffffffu, mt, o));
            const float mn = fmaxf(m_i[i], mt);
            const float alpha = __expf(m_i[i] - mn);
            m_i[i] = mn;
            float rs = 0.0f;
#pragma unroll
            for (int j = 0; j < 4; ++j) {
                s[i][j] = __expf(s[i][j] - mn);
                rs += s[i][j];
            }
#pragma unroll
            for (int o = 8; o >= 1; o >>= 1)
                rs += __shfl_xor_sync(0xffffffffu, rs, o);
            l_i[i] = l_i[i] * alpha + rs;
#pragma unroll
            for (int c = 0; c < 8; ++c) acc[i][c] *= alpha;
            // stash P
#pragma unroll
            for (int j = 0; j < 4; ++j)
                Ps[(r0 + i) * 64 + c0 + j] = s[i][j];
        }
        __syncthreads();

        // O += P @ V
#pragma unroll 4
        for (int j = 0; j < 64; ++j) {
            const float p0 = Ps[(r0 + 0) * 64 + j];
            const float p1 = Ps[(r0 + 1) * 64 + j];
            const float p2 = Ps[(r0 + 2) * 64 + j];
            const float p3 = Ps[(r0 + 3) * 64 + j];
            float4 va = *(const float4*)&Vs[j * 128 + oc];
            float4 vb = *(const float4*)&Vs[j * 128 + oc + 4];
            acc[0][0] += p0 * va.x; acc[0][1] += p0 * va.y; acc[0][2] += p0 * va.z; acc[0][3] += p0 * va.w;
            acc[0][4] += p0 * vb.x; acc[0][5] += p0 * vb.y; acc[0][6] += p0 * vb.z; acc[0][7] += p0 * vb.w;
            acc[1][0] += p1 * va.x; acc[1][1] += p1 * va.y; acc[1][2] += p1 * va.z; acc[1][3] += p1 * va.w;
            acc[1][4] += p1 * vb.x; acc[1][5] += p1 * vb.y; acc[1][6] += p1 * vb.z; acc[1][7] += p1 * vb.w;
            acc[2][0] += p2 * va.x; acc[2][1] += p2 * va.y; acc[2][2] += p2 * va.z; acc[2][3] += p2 * va.w;
            acc[2][4] += p2 * vb.x; acc[2][5] += p2 * vb.y; acc[2][6] += p2 * vb.z; acc[2][7] += p2 * vb.w;
            acc[3][0] += p3 * va.x; acc[3][1] += p3 * va.y; acc[3][2] += p3 * va.z; acc[3][3] += p3 * va.w;
            acc[3][4] += p3 * vb.x; acc[3][5] += p3 * vb.y; acc[3][6] += p3 * vb.z; acc[3][7] += p3 * vb.w;
        }
    }

    // Epilogue: O /= l, write to (B,S,H*Dh)
#pragma unroll
    for (int i = 0; i < 4; ++i) {
        const float inv = 1.0f / l_i[i];
        float* op = &g_o[(size_t)(b * NS + qb * 64 + r0 + i) * ND + h * NDH + oc];
        *(float4*)(op)     = make_float4(acc[i][0] * inv, acc[i][1] * inv,
                                         acc[i][2] * inv, acc[i][3] * inv);
        *(float4*)(op + 4) = make_float4(acc[i][4] * inv, acc[i][5] * inv,
                                         acc[i][6] * inv, acc[i][7] * inv);
    }
}

// ---------------------------------------------------------------------------
extern "C" void kernel_launch(void* const* d_in, const int* in_sizes, int n_in,
                              void* d_out, int out_size)
{
    const float* x  = (const float*)d_in[0];
    const float* fc = (const float*)d_in[1];
    const float* fs = (const float*)d_in[2];
    const float* wq = (const float*)d_in[3];
    const float* wk = (const float*)d_in[4];
    const float* wv = (const float*)d_in[5];
    const float* wo = (const float*)d_in[6];
    float* out = (float*)d_out;

    float *qb, *kb, *vb, *ob;
    cudaGetSymbolAddress((void**)&qb, g_q);
    cudaGetSymbolAddress((void**)&kb, g_k);
    cudaGetSymbolAddress((void**)&vb, g_v);
    cudaGetSymbolAddress((void**)&ob, g_o);

    // Q/K/V projections
    sgemm_nt<<<dim3(ND / 128,   NROWS / 128), 256>>>(x, wq, qb, NROWS, ND,   ND);
    sgemm_nt<<<dim3(NKVD / 128, NROWS / 128), 256>>>(x, wk, kb, NROWS, NKVD, ND);
    sgemm_nt<<<dim3(NKVD / 128, NROWS / 128), 256>>>(x, wv, vb, NROWS, NKVD, ND);

    // RoPE on q and k
    const int total_pairs = NROWS * (NH + NKVH) * (NDH / 2);
    rope_kernel<<<(total_pairs + 255) / 256, 256>>>(fc, fs);

    // Causal GQA flash attention
    cudaFuncSetAttribute(attn_kernel, cudaFuncAttributeMaxDynamicSharedMemorySize,
                         ATTN_SMEM);
    attn_kernel<<<dim3(NS / 64, NH, NB), 256, ATTN_SMEM>>>();

    // Output projection
    sgemm_nt<<<dim3(ND / 128, NROWS / 128), 256>>>(ob, wo, out, NROWS, ND, ND);
}

// round 5
// speedup vs baseline: 9.3638x; 9.3638x over previous
#include <cuda_runtime.h>
#include <cuda_fp16.h>
#include <cstdint>

// Problem constants
#define NB    2
#define NS    2048
#define ND    2048
#define NH    16
#define NKVH  4
#define NDH   128
#define NREP  (NH / NKVH)      // 4
#define NROWS (NB * NS)        // 4096
#define NKVD  (NKVH * NDH)     // 512

// fp16 scratch (static device globals: allocation-free)
__device__ __half g_xh [(size_t)NROWS * ND];    // 16 MB
__device__ __half g_wqh[(size_t)ND * ND];       //  8 MB
__device__ __half g_wkh[(size_t)NKVD * ND];     //  2 MB
__device__ __half g_wvh[(size_t)NKVD * ND];     //  2 MB
__device__ __half g_woh[(size_t)ND * ND];       //  8 MB
__device__ __half g_qh [(size_t)NROWS * ND];    // 16 MB
__device__ __half g_kh [(size_t)NROWS * NKVD];  //  4 MB
__device__ __half g_vh [(size_t)NROWS * NKVD];  //  4 MB
__device__ __half g_oh [(size_t)NROWS * ND];    // 16 MB

// ---------------------------------------------------------------------------
// mma.sync m16n8k16 fp16 -> fp32
// ---------------------------------------------------------------------------
#define MMA16816(d, a0, a1, a2, a3, b0, b1)                                  \
    asm volatile(                                                            \
        "mma.sync.aligned.m16n8k16.row.col.f32.f16.f16.f32 "                 \
        "{%0,%1,%2,%3}, {%4,%5,%6,%7}, {%8,%9}, {%0,%1,%2,%3};"              \
        : "+f"((d)[0]), "+f"((d)[1]), "+f"((d)[2]), "+f"((d)[3])             \
        : "r"(a0), "r"(a1), "r"(a2), "r"(a3), "r"(b0), "r"(b1))

#define CP_ASYNC16(dst, src)                                                 \
    asm volatile("cp.async.cg.shared.global [%0], [%1], 16;" ::              \
                 "r"(dst), "l"(src))
#define CP_COMMIT() asm volatile("cp.async.commit_group;")
#define CP_WAIT0()  asm volatile("cp.async.wait_group 0;" ::: "memory")

__device__ __forceinline__ uint32_t f2h2(float a, float b) {
    __half2 h = __floats2half2_rn(a, b);
    return *(uint32_t*)&h;
}
__device__ __forceinline__ uint32_t h2pack(__half a, __half b) {
    __half2 h = __halves2half2(a, b);
    return *(uint32_t*)&h;
}

// ---------------------------------------------------------------------------
// float -> half conversion (vectorized)
// ---------------------------------------------------------------------------
__global__ void f2h_kernel(const float* __restrict__ in, __half* __restrict__ out,
                           int n4)
{
    int i = blockIdx.x * blockDim.x + threadIdx.x;
    if (i < n4) {
        float4 v = ((const float4*)in)[i];
        __half2* o = (__half2*)out + i * 2;
        o[0] = __floats2half2_rn(v.x, v.y);
        o[1] = __floats2half2_rn(v.z, v.w);
    }
}

// ---------------------------------------------------------------------------
// HGEMM: C[M,N] = A[M,K](half,row) @ W[N,K](half,row)^T, fp32 accum.
// Block 128x128, BK=32, 256 threads (8 warps, warp tile 64x32), cp.async
// double buffering.
// ---------------------------------------------------------------------------
#define SKP 40

template <bool HALF_OUT>
__global__ __launch_bounds__(256)
void hgemm_nt(const __half* __restrict__ A, const __half* __restrict__ W,
              void* __restrict__ Cout, int M, int N, int K)
{
    __shared__ __half As[2][128][SKP];
    __shared__ __half Bs[2][128][SKP];

    const int m0 = blockIdx.y * 128;
    const int n0 = blockIdx.x * 128;
    const int t  = threadIdx.x;
    const int lane = t & 31, wid = t >> 5;
    const int wm = (wid & 1) * 64;       // warp m offset (2 rows of warps)
    const int wn = (wid >> 1) * 32;      // warp n offset (4 cols of warps)
    const int g  = lane >> 2;            // groupID
    const int c  = (lane & 3) * 2;       // in-group col base

    float acc[4][4][4];
#pragma unroll
    for (int mt = 0; mt < 4; ++mt)
#pragma unroll
        for (int nt = 0; nt < 4; ++nt)
#pragma unroll
            for (int i = 0; i < 4; ++i) acc[mt][nt][i] = 0.0f;

    const int lrow = t >> 2;      // 0..63 (x2 iters -> 0..127)
    const int lseg = t & 3;       // 8-half segment

    // --- tile loader via cp.async ---
    auto load_tile = [&](int buf, int k0) {
#pragma unroll
        for (int it = 0; it < 2; ++it) {
            const int row = lrow + it * 64;
            const __half* ga = A + (size_t)(m0 + row) * K + k0 + lseg * 8;
            uint32_t sa = (uint32_t)__cvta_generic_to_shared(&As[buf][row][lseg * 8]);
            CP_ASYNC16(sa, ga);
            const __half* gb = W + (size_t)(n0 + row) * K + k0 + lseg * 8;
            uint32_t sb = (uint32_t)__cvta_generic_to_shared(&Bs[buf][row][lseg * 8]);
            CP_ASYNC16(sb, gb);
        }
        CP_COMMIT();
    };

    const int NSTG = K / 32;
    load_tile(0, 0);

    for (int s = 0; s < NSTG; ++s) {
        CP_WAIT0();
        __syncthreads();
        if (s + 1 < NSTG) load_tile((s + 1) & 1, (s + 1) * 32);
        const int buf = s & 1;

#pragma unroll
        for (int kc = 0; kc < 32; kc += 16) {
            uint32_t a[4][4], b[4][2];
#pragma unroll
            for (int mt = 0; mt < 4; ++mt) {
                const int r = wm + mt * 16 + g;
                a[mt][0] = *(const uint32_t*)&As[buf][r][kc + c];
                a[mt][1] = *(const uint32_t*)&As[buf][r + 8][kc + c];
                a[mt][2] = *(const uint32_t*)&As[buf][r][kc + c + 8];
                a[mt][3] = *(const uint32_t*)&As[buf][r + 8][kc + c + 8];
            }
#pragma unroll
            for (int nt = 0; nt < 4; ++nt) {
                const int rn = wn + nt * 8 + g;
                b[nt][0] = *(const uint32_t*)&Bs[buf][rn][kc + c];
                b[nt][1] = *(const uint32_t*)&Bs[buf][rn][kc + c + 8];
            }
#pragma unroll
            for (int mt = 0; mt < 4; ++mt)
#pragma unroll
                for (int nt = 0; nt < 4; ++nt)
                    MMA16816(acc[mt][nt], a[mt][0], a[mt][1], a[mt][2], a[mt][3],
                             b[nt][0], b[nt][1]);
        }
        __syncthreads();
    }

    // epilogue
#pragma unroll
    for (int mt = 0; mt < 4; ++mt) {
#pragma unroll
        for (int nt = 0; nt < 4; ++nt) {
            const size_t row = (size_t)(m0 + wm + mt * 16 + g);
            const int col = n0 + wn + nt * 8 + c;
            if (HALF_OUT) {
                __half* C = (__half*)Cout;
                *(__half2*)&C[row * N + col] =
                    __floats2half2_rn(acc[mt][nt][0], acc[mt][nt][1]);
                *(__half2*)&C[(row + 8) * N + col] =
                    __floats2half2_rn(acc[mt][nt][2], acc[mt][nt][3]);
            } else {
                float* C = (float*)Cout;
                *(float2*)&C[row * N + col] =
                    make_float2(acc[mt][nt][0], acc[mt][nt][1]);
                *(float2*)&C[(row + 8) * N + col] =
                    make_float2(acc[mt][nt][2], acc[mt][nt][3]);
            }
        }
    }
}

// ---------------------------------------------------------------------------
// RoPE on fp16 q/k in place (fp32 math). Also folds 1/sqrt(Dh) into q.
// ---------------------------------------------------------------------------
__global__ void rope_h_kernel(const float* __restrict__ fc,
                              const float* __restrict__ fs)
{
    int idx = blockIdx.x * blockDim.x + threadIdx.x;
    const int QP = NROWS * NH * 64;
    const int KP = NROWS * NKVH * 64;

    __half2* base;
    int hcount;
    bool isq;
    if (idx < QP) {
        base = (__half2*)g_qh; hcount = NH; isq = true;
    } else if (idx < QP + KP) {
        idx -= QP; base = (__half2*)g_kh; hcount = NKVH; isq = false;
    } else {
        return;
    }
    const int i  = idx & 63;
    const int rh = idx >> 6;
    const int row = rh / hcount;
    const int s = row & (NS - 1);

    const float cs = fc[s * 64 + i];
    const float sn = fs[s * 64 + i];
    __half2* p = base + (size_t)rh * 64 + i;
    float2 v = __half22float2(*p);
    float orr = v.x * cs - v.y * sn;
    float oii = v.x * sn + v.y * cs;
    if (isq) { orr *= 0.08838834764831845f; oii *= 0.08838834764831845f; }
    *p = __floats2half2_rn(orr, oii);
}

// ---------------------------------------------------------------------------
// Flash attention, fp16 mma, fp32 softmax/accum, causal, GQA.
// 64 q-rows x 64 k-cols tiles, Dh=128. 4 warps; warp w owns q rows [16w,16w+16).
// smem pitch 136 halfs -> conflict-free fragment loads.
// ---------------------------------------------------------------------------
#define VP 136
#define ATTN_SMEM (3 * 64 * VP * 2)   // 52224 B

__global__ __launch_bounds__(128)
void attn_h_kernel()
{
    extern __shared__ __half sm[];
    __half (*Qs)[VP] = (__half(*)[VP])sm;
    __half (*Ks)[VP] = Qs + 64;
    __half (*Vs)[VP] = Ks + 64;

    const int qb = blockIdx.x;
    const int h  = blockIdx.y;
    const int b  = blockIdx.z;
    const int kvh = h >> 2;   // NREP = 4

    const int t = threadIdx.x;
    const int lane = t & 31, w = t >> 5;
    const int g = lane >> 2;
    const int c = (lane & 3) * 2;

    // Load Q tile (rows qb*64.., head h), coalesced float4 (8 halfs)
    for (int i = t; i < 64 * 16; i += 128) {
        const int row = i >> 4, seg = i & 15;
        *(float4*)&Qs[row][seg * 8] =
            *(const float4*)&g_qh[(size_t)(b * NS + qb * 64 + row) * ND + h * NDH + seg * 8];
    }

    float of[16][4];
#pragma unroll
    for (int nb = 0; nb < 16; ++nb)
#pragma unroll
        for (int i = 0; i < 4; ++i) of[nb][i] = 0.0f;
    float m_[2] = {-1e30f, -1e30f};
    float l_[2] = {0.0f, 0.0f};

    const int rowg0 = qb * 64 + w * 16 + g;   // global q row for rr=0

    for (int jb = 0; jb <= qb; ++jb) {
        __syncthreads();   // prior iter done with Ks/Vs
        for (int i = t; i < 64 * 16; i += 128) {
            const int row = i >> 4, seg = i & 15;
            const size_t gi =
                (size_t)(b * NS + jb * 64 + row) * NKVD + kvh * NDH + seg * 8;
            *(float4*)&Ks[row][seg * 8] = *(const float4*)&g_kh[gi];
            *(float4*)&Vs[row][seg * 8] = *(const float4*)&g_vh[gi];
        }
        __syncthreads();

        // ---- S = Q @ K^T (scale pre-folded into Q) ----
        float sc[8][4];
#pragma unroll
        for (int nb = 0; nb < 8; ++nb)
#pragma unroll
            for (int i = 0; i < 4; ++i) sc[nb][i] = 0.0f;

#pragma unroll
        for (int kc = 0; kc < 8; ++kc) {
            const int r = w * 16 + g;
            const int k0 = kc * 16;
            uint32_t a0 = *(const uint32_t*)&Qs[r][k0 + c];
            uint32_t a1 = *(const uint32_t*)&Qs[r + 8][k0 + c];
            uint32_t a2 = *(const uint32_t*)&Qs[r][k0 + c + 8];
            uint32_t a3 = *(const uint32_t*)&Qs[r + 8][k0 + c + 8];
#pragma unroll
            for (int nb = 0; nb < 8; ++nb) {
                uint32_t b0 = *(const uint32_t*)&Ks[nb * 8 + g][k0 + c];
                uint32_t b1 = *(const uint32_t*)&Ks[nb * 8 + g][k0 + c + 8];
                MMA16816(sc[nb], a0, a1, a2, a3, b0, b1);
            }
        }

        // ---- mask + online softmax ----
        const bool diag = (jb == qb);
#pragma unroll
        for (int rr = 0; rr < 2; ++rr) {
            const int rowg = rowg0 + rr * 8;
            float tm = -1e30f;
#pragma unroll
            for (int nb = 0; nb < 8; ++nb) {
                float s0 = sc[nb][rr * 2], s1 = sc[nb][rr * 2 + 1];
                if (diag) {
                    const int colg = jb * 64 + nb * 8 + c;
                    if (colg > rowg)     s0 = -1e30f;
                    if (colg + 1 > rowg) s1 = -1e30f;
                    sc[nb][rr * 2] = s0; sc[nb][rr * 2 + 1] = s1;
                }
                tm = fmaxf(tm, fmaxf(s0, s1));
            }
            tm = fmaxf(tm, __shfl_xor_sync(0xffffffffu, tm, 1));
            tm = fmaxf(tm, __shfl_xor_sync(0xffffffffu, tm, 2));
            const float mn = fmaxf(m_[rr], tm);
            const float alpha = __expf(m_[rr] - mn);
            m_[rr] = mn;
            float sum = 0.0f;
#pragma unroll
            for (int nb = 0; nb < 8; ++nb) {
                const float p0 = __expf(sc[nb][rr * 2] - mn);
                const float p1 = __expf(sc[nb][rr * 2 + 1] - mn);
                sc[nb][rr * 2] = p0; sc[nb][rr * 2 + 1] = p1;
                sum += p0 + p1;
            }
            sum += __shfl_xor_sync(0xffffffffu, sum, 1);
            sum += __shfl_xor_sync(0xffffffffu, sum, 2);
            l_[rr] = l_[rr] * alpha + sum;
#pragma unroll
            for (int nb = 0; nb < 16; ++nb) {
                of[nb][rr * 2]     *= alpha;
                of[nb][rr * 2 + 1] *= alpha;
            }
        }

        // ---- O += P @ V  (P re-used from S fragments: C-frag == A-frag layout) ----
        uint32_t pa[4][4];
#pragma unroll
        for (int k2 = 0; k2 < 4; ++k2) {
            pa[k2][0] = f2h2(sc[2 * k2][0],     sc[2 * k2][1]);
            pa[k2][1] = f2h2(sc[2 * k2][2],     sc[2 * k2][3]);
            pa[k2][2] = f2h2(sc[2 * k2 + 1][0], sc[2 * k2 + 1][1]);
            pa[k2][3] = f2h2(sc[2 * k2 + 1][2], sc[2 * k2 + 1][3]);
        }
#pragma unroll
        for (int k2 = 0; k2 < 4; ++k2) {
            const int k0 = k2 * 16 + c;
#pragma unroll
            for (int nb = 0; nb < 16; ++nb) {
                const int n = nb * 8 + g;
                uint32_t b0 = h2pack(Vs[k0][n],     Vs[k0 + 1][n]);
                uint32_t b1 = h2pack(Vs[k0 + 8][n], Vs[k0 + 9][n]);
                MMA16816(of[nb], pa[k2][0], pa[k2][1], pa[k2][2], pa[k2][3], b0, b1);
            }
        }
    }

    // epilogue: normalize, write half
    const float inv0 = 1.0f / l_[0];
    const float inv1 = 1.0f / l_[1];
    const size_t row = (size_t)(b * NS + qb * 64 + w * 16 + g);
#pragma unroll
    for (int nb = 0; nb < 16; ++nb) {
        const int col = h * NDH + nb * 8 + c;
        *(__half2*)&g_oh[row * ND + col] =
            __floats2half2_rn(of[nb][0] * inv0, of[nb][1] * inv0);
        *(__half2*)&g_oh[(row + 8) * ND + col] =
            __floats2half2_rn(of[nb][2] * inv1, of[nb][3] * inv1);
    }
}

// ---------------------------------------------------------------------------
extern "C" void kernel_launch(void* const* d_in, const int* in_sizes, int n_in,
                              void* d_out, int out_size)
{
    const float* x  = (const float*)d_in[0];
    const float* fc = (const float*)d_in[1];
    const float* fs = (const float*)d_in[2];
    const float* wq = (const float*)d_in[3];
    const float* wk = (const float*)d_in[4];
    const float* wv = (const float*)d_in[5];
    const float* wo = (const float*)d_in[6];
    float* out = (float*)d_out;

    __half *xh, *wqh, *wkh, *wvh, *woh, *qh, *kh, *vh, *oh;
    cudaGetSymbolAddress((void**)&xh,  g_xh);
    cudaGetSymbolAddress((void**)&wqh, g_wqh);
    cudaGetSymbolAddress((void**)&wkh, g_wkh);
    cudaGetSymbolAddress((void**)&wvh, g_wvh);
    cudaGetSymbolAddress((void**)&woh, g_woh);
    cudaGetSymbolAddress((void**)&qh,  g_qh);
    cudaGetSymbolAddress((void**)&kh,  g_kh);
    cudaGetSymbolAddress((void**)&vh,  g_vh);
    cudaGetSymbolAddress((void**)&oh,  g_oh);

    // fp32 -> fp16 conversions
    const int nx = NROWS * ND / 4, nwq = ND * ND / 4, nwkv = NKVD * ND / 4;
    f2h_kernel<<<(nx   + 255) / 256, 256>>>(x,  xh,  nx);
    f2h_kernel<<<(nwq  + 255) / 256, 256>>>(wq, wqh, nwq);
    f2h_kernel<<<(nwkv + 255) / 256, 256>>>(wk, wkh, nwkv);
    f2h_kernel<<<(nwkv + 255) / 256, 256>>>(wv, wvh, nwkv);
    f2h_kernel<<<(nwq  + 255) / 256, 256>>>(wo, woh, nwq);

    // Q/K/V projections (fp16 tensor-core GEMMs, half output)
    hgemm_nt<true><<<dim3(ND / 128,   NROWS / 128), 256>>>(xh, wqh, qh, NROWS, ND,   ND);
    hgemm_nt<true><<<dim3(NKVD / 128, NROWS / 128), 256>>>(xh, wkh, kh, NROWS, NKVD, ND);
    hgemm_nt<true><<<dim3(NKVD / 128, NROWS / 128), 256>>>(xh, wvh, vh, NROWS, NKVD, ND);

    // RoPE on q and k (q pre-scaled by 1/sqrt(Dh))
    const int total_pairs = NROWS * (NH + NKVH) * (NDH / 2);
    rope_h_kernel<<<(total_pairs + 255) / 256, 256>>>(fc, fs);

    // Causal GQA flash attention (fp16 mma)
    cudaFuncSetAttribute(attn_h_kernel,
                         cudaFuncAttributeMaxDynamicSharedMemorySize, ATTN_SMEM);
    attn_h_kernel<<<dim3(NS / 64, NH, NB), 128, ATTN_SMEM>>>();

    // Output projection (fp32 output)
    hgemm_nt<false><<<dim3(ND / 128, NROWS / 128), 256>>>(oh, woh, out, NROWS, ND, ND);
}

// round 10
// speedup vs baseline: 10.7435x; 1.1473x over previous
#include <cuda_runtime.h>
#include <cuda_fp16.h>
#include <cstdint>

// Problem constants
#define NB    2
#define NS    2048
#define ND    2048
#define NH    16
#define NKVH  4
#define NDH   128
#define NROWS (NB * NS)        // 4096
#define NQKV  3072             // 2048 q + 512 k + 512 v

// fp16 scratch (static device globals: allocation-free)
__device__ __half g_xh   [(size_t)NROWS * ND];    // 16 MB
__device__ __half g_wqkvh[(size_t)NQKV * ND];     // 12 MB  (wq | wk | wv rows)
__device__ __half g_woh  [(size_t)ND * ND];       //  8 MB
__device__ __half g_qkvh [(size_t)NROWS * NQKV];  // 24 MB  row: [q 2048 | k 512 | v 512]
__device__ __half g_oh   [(size_t)NROWS * ND];    // 16 MB

// ---------------------------------------------------------------------------
// PTX helpers
// ---------------------------------------------------------------------------
#define MMA16816(d, a0, a1, a2, a3, b0, b1)                                  \
    asm volatile(                                                            \
        "mma.sync.aligned.m16n8k16.row.col.f32.f16.f16.f32 "                 \
        "{%0,%1,%2,%3}, {%4,%5,%6,%7}, {%8,%9}, {%0,%1,%2,%3};"              \
        : "+f"((d)[0]), "+f"((d)[1]), "+f"((d)[2]), "+f"((d)[3])             \
        : "r"(a0), "r"(a1), "r"(a2), "r"(a3), "r"(b0), "r"(b1))

#define CP_ASYNC16(dst, src)                                                 \
    asm volatile("cp.async.cg.shared.global [%0], [%1], 16;" ::              \
                 "r"(dst), "l"(src))
#define CP_COMMIT() asm volatile("cp.async.commit_group;")
#define CP_WAIT0()  asm volatile("cp.async.wait_group 0;" ::: "memory")
#define CP_WAIT1()  asm volatile("cp.async.wait_group 1;" ::: "memory")

#define LDSM_X4(r0, r1, r2, r3, a)                                           \
    asm volatile("ldmatrix.sync.aligned.m8n8.x4.shared.b16 "                 \
                 "{%0,%1,%2,%3}, [%4];"                                      \
                 : "=r"(r0), "=r"(r1), "=r"(r2), "=r"(r3) : "r"(a))
#define LDSM_X4T(r0, r1, r2, r3, a)                                          \
    asm volatile("ldmatrix.sync.aligned.m8n8.x4.trans.shared.b16 "           \
                 "{%0,%1,%2,%3}, [%4];"                                      \
                 : "=r"(r0), "=r"(r1), "=r"(r2), "=r"(r3) : "r"(a))

__device__ __forceinline__ uint32_t s2u(const void* p) {
    return (uint32_t)__cvta_generic_to_shared(p);
}
__device__ __forceinline__ uint32_t f2h2(float a, float b) {
    __half2 h = __floats2half2_rn(a, b);
    return *(uint32_t*)&h;
}

// ---------------------------------------------------------------------------
// float -> half conversion
// ---------------------------------------------------------------------------
__global__ void f2h_kernel(const float* __restrict__ in, __half* __restrict__ out,
                           int n4)
{
    int i = blockIdx.x * blockDim.x + threadIdx.x;
    if (i < n4) {
        float4 v = ((const float4*)in)[i];
        __half2* o = (__half2*)out + i * 2;
        o[0] = __floats2half2_rn(v.x, v.y);
        o[1] = __floats2half2_rn(v.z, v.w);
    }
}

// ---------------------------------------------------------------------------
// HGEMM: C[M,N] = A[M,K](half,row) @ W[N,K](half,row)^T, fp32 accum.
// CTA tile 128x128, BK=32, 128 threads (4 warps, warp tile 64x64),
// 3-stage cp.async ring, ldmatrix fragment loads.
// ---------------------------------------------------------------------------
#define SKP 40
#define GEMM_SMEM (2 * 3 * 128 * SKP * 2)   // 61440 B

template <bool HALF_OUT>
__global__ __launch_bounds__(128)
void hgemm_nt(const __half* __restrict__ A, const __half* __restrict__ W,
              void* __restrict__ Cout, int M, int N, int K)
{
    extern __shared__ __half hsm[];
    __half (*As)[128][SKP] = (__half(*)[128][SKP])hsm;
    __half (*Bs)[128][SKP] = (__half(*)[128][SKP])(hsm + 3 * 128 * SKP);

    const int m0 = blockIdx.y * 128;
    const int n0 = blockIdx.x * 128;
    const int t  = threadIdx.x;
    const int lane = t & 31, wid = t >> 5;
    const int wm = (wid & 1) * 64;
    const int wn = (wid >> 1) * 64;
    const int g  = lane >> 2;
    const int c  = (lane & 3) * 2;
    const int l15 = lane & 15, l16 = (lane >> 4) * 8;

    float acc[4][8][4];
#pragma unroll
    for (int mt = 0; mt < 4; ++mt)
#pragma unroll
        for (int nb = 0; nb < 8; ++nb)
#pragma unroll
            for (int i = 0; i < 4; ++i) acc[mt][nb][i] = 0.0f;

    const int lr = t >> 2, lseg = (t & 3) * 8;

    auto load_tile = [&](int buf, int k0) {
#pragma unroll
        for (int it = 0; it < 4; ++it) {
            const int row = lr + it * 32;
            CP_ASYNC16(s2u(&As[buf][row][lseg]),
                       A + (size_t)(m0 + row) * K + k0 + lseg);
            CP_ASYNC16(s2u(&Bs[buf][row][lseg]),
                       W + (size_t)(n0 + row) * K + k0 + lseg);
        }
    };

    const int NSTG = K / 32;
    load_tile(0, 0);  CP_COMMIT();
    load_tile(1, 32); CP_COMMIT();

    for (int s = 0; s < NSTG; ++s) {
        CP_WAIT1();
        __syncthreads();
        if (s + 2 < NSTG) load_tile((s + 2) % 3, (s + 2) * 32);
        CP_COMMIT();
        const int buf = s % 3;

#pragma unroll
        for (int kc = 0; kc < 32; kc += 16) {
            uint32_t a[4][4], b[4][4];
#pragma unroll
            for (int mt = 0; mt < 4; ++mt)
                LDSM_X4(a[mt][0], a[mt][1], a[mt][2], a[mt][3],
                        s2u(&As[buf][wm + mt * 16 + l15][kc + l16]));
#pragma unroll
            for (int nt = 0; nt < 4; ++nt)
                LDSM_X4(b[nt][0], b[nt][1], b[nt][2], b[nt][3],
                        s2u(&Bs[buf][wn + nt * 16 + l15][kc + l16]));
            // b[nt][0]=b0(n), b[nt][1]=b0(n+8), b[nt][2]=b1(n), b[nt][3]=b1(n+8)
#pragma unroll
            for (int mt = 0; mt < 4; ++mt)
#pragma unroll
                for (int nb = 0; nb < 8; ++nb)
                    MMA16816(acc[mt][nb],
                             a[mt][0], a[mt][1], a[mt][2], a[mt][3],
                             b[nb >> 1][nb & 1], b[nb >> 1][2 + (nb & 1)]);
        }
    }

    // epilogue
#pragma unroll
    for (int mt = 0; mt < 4; ++mt) {
#pragma unroll
        for (int nb = 0; nb < 8; ++nb) {
            const size_t row = (size_t)(m0 + wm + mt * 16 + g);
            const int col = n0 + wn + nb * 8 + c;
            if (HALF_OUT) {
                __half* C = (__half*)Cout;
                *(__half2*)&C[row * N + col] =
                    __floats2half2_rn(acc[mt][nb][0], acc[mt][nb][1]);
                *(__half2*)&C[(row + 8) * N + col] =
                    __floats2half2_rn(acc[mt][nb][2], acc[mt][nb][3]);
            } else {
                float* C = (float*)Cout;
                *(float2*)&C[row * N + col] =
                    make_float2(acc[mt][nb][0], acc[mt][nb][1]);
                *(float2*)&C[(row + 8) * N + col] =
                    make_float2(acc[mt][nb][2], acc[mt][nb][3]);
            }
        }
    }
}

// ---------------------------------------------------------------------------
// RoPE on fused qkv buffer (fp32 math). Folds 1/sqrt(Dh) into q.
// ---------------------------------------------------------------------------
__global__ void rope_h_kernel(const float* __restrict__ fc,
                              const float* __restrict__ fs)
{
    int idx = blockIdx.x * blockDim.x + threadIdx.x;
    const int QP = NROWS * NH * 64;
    const int KP = NROWS * NKVH * 64;
    __half2* qkv = (__half2*)g_qkvh;   // row stride 1536 half2

    __half2* p;
    int s, i;
    bool isq;
    if (idx < QP) {
        i = idx & 63;
        const int rh = idx >> 6;
        const int row = rh >> 4, h = rh & 15;
        s = row & (NS - 1);
        p = qkv + (size_t)row * 1536 + h * 64 + i;
        isq = true;
    } else if (idx < QP + KP) {
        idx -= QP;
        i = idx & 63;
        const int rh = idx >> 6;
        const int row = rh >> 2, kvh = rh & 3;
        s = row & (NS - 1);
        p = qkv + (size_t)row * 1536 + 1024 + kvh * 64 + i;
        isq = false;
    } else {
        return;
    }

    const float cs = fc[s * 64 + i];
    const float sn = fs[s * 64 + i];
    float2 v = __half22float2(*p);
    float orr = v.x * cs - v.y * sn;
    float oii = v.x * sn + v.y * cs;
    if (isq) { orr *= 0.08838834764831845f; oii *= 0.08838834764831845f; }
    *p = __floats2half2_rn(orr, oii);
}

// ---------------------------------------------------------------------------
// Flash attention: 128 q-rows x 64 kv-cols per CTA, 8 warps, Dh=128.
// Q fragments hoisted; K/V fragments via ldmatrix (trans for V);
// cp.async double-buffered KV tiles. fp32 softmax/accum.
// ---------------------------------------------------------------------------
#define VP 136
#define ATTN_SMEM ((128 + 4 * 64) * VP * 2)   // 104448 B

__global__ __launch_bounds__(256)
void attn_h_kernel()
{
    extern __shared__ __half sm[];
    __half (*Qs)[VP]     = (__half(*)[VP])sm;                      // [128][VP]
    __half (*Ks)[64][VP] = (__half(*)[64][VP])(sm + 128 * VP);     // [2][64][VP]
    __half (*Vs)[64][VP] = (__half(*)[64][VP])(sm + 256 * VP);     // [2][64][VP]

    const int qb = (int)gridDim.x - 1 - (int)blockIdx.x;  // big tiles first
    const int h  = blockIdx.y;
    const int b  = blockIdx.z;
    const int kvh = h >> 2;

    const int t = threadIdx.x;
    const int lane = t & 31, w = t >> 5;
    const int g = lane >> 2;
    const int c = (lane & 3) * 2;
    const int l15 = lane & 15, l16 = (lane >> 4) * 8;

    const __half* qkv = g_qkvh;

    auto load_kv = [&](int buf, int jb) {
#pragma unroll
        for (int it = 0; it < 4; ++it) {
            const int i = t + it * 256;
            const int row = i >> 4, seg = (i & 15) * 8;
            const size_t grow = (size_t)(b * NS + jb * 64 + row) * NQKV + kvh * NDH + seg;
            CP_ASYNC16(s2u(&Ks[buf][row][seg]), qkv + grow + 2048);
            CP_ASYNC16(s2u(&Vs[buf][row][seg]), qkv + grow + 2560);
        }
    };

    // Q tile (128 rows, head h) + first KV tile
#pragma unroll
    for (int it = 0; it < 8; ++it) {
        const int i = t + it * 256;
        const int row = i >> 4, seg = (i & 15) * 8;
        CP_ASYNC16(s2u(&Qs[row][seg]),
                   qkv + (size_t)(b * NS + qb * 128 + row) * NQKV + h * NDH + seg);
    }
    load_kv(0, 0);
    CP_COMMIT();
    CP_WAIT0();
    __syncthreads();

    // Hoist Q fragments (loop-invariant)
    uint32_t qa[8][4];
#pragma unroll
    for (int kc = 0; kc < 8; ++kc)
        LDSM_X4(qa[kc][0], qa[kc][1], qa[kc][2], qa[kc][3],
                s2u(&Qs[w * 16 + l15][kc * 16 + l16]));

    float of[16][4];
#pragma unroll
    for (int nb = 0; nb < 16; ++nb)
#pragma unroll
        for (int i = 0; i < 4; ++i) of[nb][i] = 0.0f;
    float m_[2] = {-1e30f, -1e30f};
    float l_[2] = {0.0f, 0.0f};

    const int jmax = 2 * qb + 1;
    const int warp_row0 = qb * 128 + w * 16;

    for (int jb = 0; jb <= jmax; ++jb) {
        __syncthreads();   // all warps done with buf (jb-1)&1; buf jb published
        if (jb + 1 <= jmax) load_kv((jb + 1) & 1, jb + 1);
        CP_COMMIT();
        const int buf = jb & 1;

        // ---- S = Q @ K^T ----
        float sc[8][4];
#pragma unroll
        for (int nb = 0; nb < 8; ++nb)
#pragma unroll
            for (int i = 0; i < 4; ++i) sc[nb][i] = 0.0f;

#pragma unroll
        for (int kc = 0; kc < 8; ++kc) {
#pragma unroll
            for (int nt = 0; nt < 4; ++nt) {
                uint32_t k0, k1, k2, k3;
                LDSM_X4(k0, k1, k2, k3,
                        s2u(&Ks[buf][nt * 16 + l15][kc * 16 + l16]));
                MMA16816(sc[nt * 2],     qa[kc][0], qa[kc][1], qa[kc][2], qa[kc][3], k0, k2);
                MMA16816(sc[nt * 2 + 1], qa[kc][0], qa[kc][1], qa[kc][2], qa[kc][3], k1, k3);
            }
        }

        // ---- mask + online softmax ----
        const bool needmask = (jb * 64 + 63 > warp_row0);
#pragma unroll
        for (int rr = 0; rr < 2; ++rr) {
            const int rowg = warp_row0 + g + rr * 8;
            float tm = -1e30f;
#pragma unroll
            for (int nb = 0; nb < 8; ++nb) {
                float s0 = sc[nb][rr * 2], s1 = sc[nb][rr * 2 + 1];
                if (needmask) {
                    const int colg = jb * 64 + nb * 8 + c;
                    if (colg > rowg)     s0 = -1e30f;
                    if (colg + 1 > rowg) s1 = -1e30f;
                    sc[nb][rr * 2] = s0; sc[nb][rr * 2 + 1] = s1;
                }
                tm = fmaxf(tm, fmaxf(s0, s1));
            }
            tm = fmaxf(tm, __shfl_xor_sync(0xffffffffu, tm, 1));
            tm = fmaxf(tm, __shfl_xor_sync(0xffffffffu, tm, 2));
            const float mn = fmaxf(m_[rr], tm);
            const float alpha = __expf(m_[rr] - mn);
            m_[rr] = mn;
            float sum = 0.0f;
#pragma unroll
            for (int nb = 0; nb < 8; ++nb) {
                const float p0 = __expf(sc[nb][rr * 2] - mn);
                const float p1 = __expf(sc[nb][rr * 2 + 1] - mn);
                sc[nb][rr * 2] = p0; sc[nb][rr * 2 + 1] = p1;
                sum += p0 + p1;
            }
            sum += __shfl_xor_sync(0xffffffffu, sum, 1);
            sum += __shfl_xor_sync(0xffffffffu, sum, 2);
            l_[rr] = l_[rr] * alpha + sum;
#pragma unroll
            for (int nb = 0; nb < 16; ++nb) {
                of[nb][rr * 2]     *= alpha;
                of[nb][rr * 2 + 1] *= alpha;
            }
        }

        // ---- O += P @ V ----
        uint32_t pa[4][4];
#pragma unroll
        for (int k2 = 0; k2 < 4; ++k2) {
            pa[k2][0] = f2h2(sc[2 * k2][0],     sc[2 * k2][1]);
            pa[k2][1] = f2h2(sc[2 * k2][2],     sc[2 * k2][3]);
            pa[k2][2] = f2h2(sc[2 * k2 + 1][0], sc[2 * k2 + 1][1]);
            pa[k2][3] = f2h2(sc[2 * k2 + 1][2], sc[2 * k2 + 1][3]);
        }
#pragma unroll
        for (int k2 = 0; k2 < 4; ++k2) {
#pragma unroll
            for (int nt = 0; nt < 8; ++nt) {
                uint32_t v0, v1, v2, v3;
                LDSM_X4T(v0, v1, v2, v3,
                         s2u(&Vs[buf][k2 * 16 + l15][nt * 16 + l16]));
                MMA16816(of[nt * 2],     pa[k2][0], pa[k2][1], pa[k2][2], pa[k2][3], v0, v1);
                MMA16816(of[nt * 2 + 1], pa[k2][0], pa[k2][1], pa[k2][2], pa[k2][3], v2, v3);
            }
        }

        CP_WAIT0();   // next KV tile landed (overlapped with compute above)
    }

    // epilogue: normalize, write half
    const float inv0 = 1.0f / l_[0];
    const float inv1 = 1.0f / l_[1];
    const size_t row = (size_t)(b * NS + qb * 128 + w * 16 + g);
#pragma unroll
    for (int nb = 0; nb < 16; ++nb) {
        const int col = h * NDH + nb * 8 + c;
        *(__half2*)&g_oh[row * ND + col] =
            __floats2half2_rn(of[nb][0] * inv0, of[nb][1] * inv0);
        *(__half2*)&g_oh[(row + 8) * ND + col] =
            __floats2half2_rn(of[nb][2] * inv1, of[nb][3] * inv1);
    }
}

// ---------------------------------------------------------------------------
extern "C" void kernel_launch(void* const* d_in, const int* in_sizes, int n_in,
                              void* d_out, int out_size)
{
    const float* x  = (const float*)d_in[0];
    const float* fc = (const float*)d_in[1];
    const float* fs = (const float*)d_in[2];
    const float* wq = (const float*)d_in[3];
    const float* wk = (const float*)d_in[4];
    const float* wv = (const float*)d_in[5];
    const float* wo = (const float*)d_in[6];
    float* out = (float*)d_out;

    __half *xh, *wqkvh, *woh, *qkvh, *oh;
    cudaGetSymbolAddress((void**)&xh,    g_xh);
    cudaGetSymbolAddress((void**)&wqkvh, g_wqkvh);
    cudaGetSymbolAddress((void**)&woh,   g_woh);
    cudaGetSymbolAddress((void**)&qkvh,  g_qkvh);
    cudaGetSymbolAddress((void**)&oh,    g_oh);

    // fp32 -> fp16 conversions (wq|wk|wv concatenated into g_wqkvh)
    const int nx  = NROWS * ND / 4;
    const int nwq = ND * ND / 4;
    const int nkv = 512 * 2048 / 4;
    f2h_kernel<<<(nx  + 255) / 256, 256>>>(x,  xh, nx);
    f2h_kernel<<<(nwq + 255) / 256, 256>>>(wq, wqkvh, nwq);
    f2h_kernel<<<(nkv + 255) / 256, 256>>>(wk, wqkvh + (size_t)2048 * 2048, nkv);
    f2h_kernel<<<(nkv + 255) / 256, 256>>>(wv, wqkvh + (size_t)2560 * 2048, nkv);
    f2h_kernel<<<(nwq + 255) / 256, 256>>>(wo, woh, nwq);

    // Fused QKV projection: [4096,2048] @ [3072,2048]^T -> [4096,3072] half
    cudaFuncSetAttribute(hgemm_nt<true>,
                         cudaFuncAttributeMaxDynamicSharedMemorySize, GEMM_SMEM);
    cudaFuncSetAttribute(hgemm_nt<false>,
                         cudaFuncAttributeMaxDynamicSharedMemorySize, GEMM_SMEM);
    hgemm_nt<true><<<dim3(NQKV / 128, NROWS / 128), 128, GEMM_SMEM>>>(
        xh, wqkvh, qkvh, NROWS, NQKV, ND);

    // RoPE (q pre-scaled by 1/sqrt(Dh))
    const int total_pairs = NROWS * (NH + NKVH) * 64;
    rope_h_kernel<<<(total_pairs + 255) / 256, 256>>>(fc, fs);

    // Causal GQA flash attention
    cudaFuncSetAttribute(attn_h_kernel,
                         cudaFuncAttributeMaxDynamicSharedMemorySize, ATTN_SMEM);
    attn_h_kernel<<<dim3(NS / 128, NH, NB), 256, ATTN_SMEM>>>();

    // Output projection (fp32 output)
    hgemm_nt<false><<<dim3(ND / 128, NROWS / 128), 128, GEMM_SMEM>>>(
        oh, woh, out, NROWS, ND, ND);
}